// round 1
// baseline (speedup 1.0000x reference)
#include <cuda_runtime.h>

#define BB 4
#define NN 50000
#define DD 256
#define EE 800000
#define TAU_MIN_F 0.001f
#define MAX_CORR_F 0.15f
#define XPBD_ITERS_I 4

// Ping-pong point buffers, padded to float4 for single-LDG gathers.
// 2 * 200000 * 16B = 6.4 MB (fits in L2 comfortably).
__device__ float4 g_x[2][BB * NN];

// ---------------------------------------------------------------------------
// Kernel 1: x_pred = keypoints + tau * (hand_tokens @ head_w + head_b)
// warp-per-row; head_w staged in shared memory. HBM-bound on hand_tokens.
// ---------------------------------------------------------------------------
__global__ void pred_kernel(const float* __restrict__ keypoints,
                            const float* __restrict__ timesteps,
                            const float* __restrict__ hand_tokens,
                            const float* __restrict__ head_w,
                            const float* __restrict__ head_b) {
    __shared__ float sw[DD * 3];
    int tid = threadIdx.x;
    for (int i = tid; i < DD * 3; i += blockDim.x) sw[i] = head_w[i];
    __syncthreads();

    int warp = (int)((blockIdx.x * (size_t)blockDim.x + tid) >> 5);
    int lane = tid & 31;
    if (warp >= BB * NN) return;

    const float4* hrow =
        reinterpret_cast<const float4*>(hand_tokens + (size_t)warp * DD);
    float4 a = hrow[lane];        // d = 4*lane .. 4*lane+3
    float4 c = hrow[lane + 32];   // d = 128 + 4*lane ..

    float acc0 = 0.f, acc1 = 0.f, acc2 = 0.f;
    int d0 = lane * 4;
    {
        const float* w = &sw[d0 * 3];
        acc0 += a.x * w[0] + a.y * w[3] + a.z * w[6] + a.w * w[9];
        acc1 += a.x * w[1] + a.y * w[4] + a.z * w[7] + a.w * w[10];
        acc2 += a.x * w[2] + a.y * w[5] + a.z * w[8] + a.w * w[11];
    }
    {
        const float* w = &sw[(d0 + 128) * 3];
        acc0 += c.x * w[0] + c.y * w[3] + c.z * w[6] + c.w * w[9];
        acc1 += c.x * w[1] + c.y * w[4] + c.z * w[7] + c.w * w[10];
        acc2 += c.x * w[2] + c.y * w[5] + c.z * w[8] + c.w * w[11];
    }

#pragma unroll
    for (int off = 16; off > 0; off >>= 1) {
        acc0 += __shfl_xor_sync(0xFFFFFFFFu, acc0, off);
        acc1 += __shfl_xor_sync(0xFFFFFFFFu, acc1, off);
        acc2 += __shfl_xor_sync(0xFFFFFFFFu, acc2, off);
    }

    if (lane == 0) {
        int b = warp / NN;
        float tau = fmaxf(1.0f - timesteps[b], TAU_MIN_F);
        size_t o = 3 * (size_t)warp;
        float kx = keypoints[o + 0];
        float ky = keypoints[o + 1];
        float kz = keypoints[o + 2];
        g_x[0][warp] = make_float4(kx + tau * (acc0 + head_b[0]),
                                   ky + tau * (acc1 + head_b[1]),
                                   kz + tau * (acc2 + head_b[2]), 0.f);
    }
}

// ---------------------------------------------------------------------------
// Kernel 2: x_next = x_cur  (Jacobi double-buffer init)
// ---------------------------------------------------------------------------
__global__ void copy_kernel(int cur, int nxt) {
    int i = blockIdx.x * blockDim.x + threadIdx.x;
    if (i < BB * NN) g_x[nxt][i] = g_x[cur][i];
}

// ---------------------------------------------------------------------------
// Kernel 3: one XPBD Jacobi iteration. Thread per edge, loop over batches
// (amortizes src/dst/L0 loads). Reads x_cur, scatter-adds into x_next.
// ---------------------------------------------------------------------------
__global__ void edge_kernel(const int* __restrict__ edge_index,
                            const float* __restrict__ rest,
                            int cur, int nxt) {
    int e = blockIdx.x * blockDim.x + threadIdx.x;
    if (e >= EE) return;
    int s = edge_index[e];
    int d = edge_index[EE + e];
    float L0 = rest[e];
    const float denom = 2.0f;  // w_i+w_j+alpha+1e-9 rounds to 2.0 in fp32

#pragma unroll
    for (int b = 0; b < BB; b++) {
        float4 xs = g_x[cur][b * NN + s];
        float4 xd = g_x[cur][b * NN + d];
        float dx = xs.x - xd.x;
        float dy = xs.y - xd.y;
        float dz = xs.z - xd.z;
        float dist = sqrtf(dx * dx + dy * dy + dz * dz);
        float inv = 1.0f / (dist + 1e-9f);
        float dl = -(dist - L0) / denom;
        float f = dl * inv;
        float cx = fminf(fmaxf(f * dx, -MAX_CORR_F), MAX_CORR_F);
        float cy = fminf(fmaxf(f * dy, -MAX_CORR_F), MAX_CORR_F);
        float cz = fminf(fmaxf(f * dz, -MAX_CORR_F), MAX_CORR_F);
        float* ps = reinterpret_cast<float*>(&g_x[nxt][b * NN + s]);
        float* pd = reinterpret_cast<float*>(&g_x[nxt][b * NN + d]);
        atomicAdd(ps + 0, cx);
        atomicAdd(ps + 1, cy);
        atomicAdd(ps + 2, cz);
        atomicAdd(pd + 0, -cx);
        atomicAdd(pd + 1, -cy);
        atomicAdd(pd + 2, -cz);
    }
}

// ---------------------------------------------------------------------------
// Kernel 4: v_eff = (x_corrected - keypoints) / tau
// ---------------------------------------------------------------------------
__global__ void final_kernel(const float* __restrict__ keypoints,
                             const float* __restrict__ timesteps,
                             float* __restrict__ out, int cur) {
    int i = blockIdx.x * blockDim.x + threadIdx.x;
    if (i >= BB * NN) return;
    int b = i / NN;
    float tau = fmaxf(1.0f - timesteps[b], TAU_MIN_F);
    float4 x = g_x[cur][i];
    size_t o = 3 * (size_t)i;
    out[o + 0] = (x.x - keypoints[o + 0]) / tau;
    out[o + 1] = (x.y - keypoints[o + 1]) / tau;
    out[o + 2] = (x.z - keypoints[o + 2]) / tau;
}

extern "C" void kernel_launch(void* const* d_in, const int* in_sizes, int n_in,
                              void* d_out, int out_size) {
    const float* keypoints = (const float*)d_in[0];
    const float* timesteps = (const float*)d_in[1];
    const float* hand_tokens = (const float*)d_in[2];
    const float* head_w = (const float*)d_in[3];
    const float* head_b = (const float*)d_in[4];
    const int* edge_index = (const int*)d_in[5];
    const float* rest = (const float*)d_in[6];
    float* out = (float*)d_out;

    const int rows = BB * NN;  // 200000

    // Phase 1: prediction head (warp per row)
    {
        long long threads = (long long)rows * 32;
        int blk = 256;
        int grid = (int)((threads + blk - 1) / blk);
        pred_kernel<<<grid, blk>>>(keypoints, timesteps, hand_tokens, head_w,
                                   head_b);
    }

    // Phase 2: XPBD Jacobi iterations
    int cur = 0;
    for (int it = 0; it < XPBD_ITERS_I; it++) {
        int nxt = cur ^ 1;
        copy_kernel<<<(rows + 255) / 256, 256>>>(cur, nxt);
        edge_kernel<<<(EE + 255) / 256, 256>>>(edge_index, rest, cur, nxt);
        cur = nxt;
    }

    // Phase 3: effective velocity
    final_kernel<<<(rows + 255) / 256, 256>>>(keypoints, timesteps, out, cur);
}

// round 2
// speedup vs baseline: 1.9082x; 1.9082x over previous
#include <cuda_runtime.h>

#define BB 4
#define NN 50000
#define DD 256
#define EE 800000
#define TAU_MIN_F 0.001f
#define MAX_CORR_F 0.15f
#define XPBD_ITERS_I 4

// Ping-pong point buffers, padded to float4 for single-LDG gathers and
// 16B-aligned vector atomics. 2 * 200000 * 16B = 6.4 MB (L2-resident).
__device__ float4 g_x[2][BB * NN];

// ---------------------------------------------------------------------------
// Kernel 1: x_pred = keypoints + tau * (hand_tokens @ head_w + head_b)
// warp-per-row; head_w staged in shared memory. HBM-bound on hand_tokens.
// ---------------------------------------------------------------------------
__global__ void pred_kernel(const float* __restrict__ keypoints,
                            const float* __restrict__ timesteps,
                            const float* __restrict__ hand_tokens,
                            const float* __restrict__ head_w,
                            const float* __restrict__ head_b) {
    __shared__ float sw[DD * 3];
    int tid = threadIdx.x;
    for (int i = tid; i < DD * 3; i += blockDim.x) sw[i] = head_w[i];
    __syncthreads();

    int warp = (int)((blockIdx.x * (size_t)blockDim.x + tid) >> 5);
    int lane = tid & 31;
    if (warp >= BB * NN) return;

    const float4* hrow =
        reinterpret_cast<const float4*>(hand_tokens + (size_t)warp * DD);
    float4 a = hrow[lane];        // d = 4*lane .. 4*lane+3
    float4 c = hrow[lane + 32];   // d = 128 + 4*lane ..

    float acc0 = 0.f, acc1 = 0.f, acc2 = 0.f;
    int d0 = lane * 4;
    {
        const float* w = &sw[d0 * 3];
        acc0 += a.x * w[0] + a.y * w[3] + a.z * w[6] + a.w * w[9];
        acc1 += a.x * w[1] + a.y * w[4] + a.z * w[7] + a.w * w[10];
        acc2 += a.x * w[2] + a.y * w[5] + a.z * w[8] + a.w * w[11];
    }
    {
        const float* w = &sw[(d0 + 128) * 3];
        acc0 += c.x * w[0] + c.y * w[3] + c.z * w[6] + c.w * w[9];
        acc1 += c.x * w[1] + c.y * w[4] + c.z * w[7] + c.w * w[10];
        acc2 += c.x * w[2] + c.y * w[5] + c.z * w[8] + c.w * w[11];
    }

#pragma unroll
    for (int off = 16; off > 0; off >>= 1) {
        acc0 += __shfl_xor_sync(0xFFFFFFFFu, acc0, off);
        acc1 += __shfl_xor_sync(0xFFFFFFFFu, acc1, off);
        acc2 += __shfl_xor_sync(0xFFFFFFFFu, acc2, off);
    }

    if (lane == 0) {
        int b = warp / NN;
        float tau = fmaxf(1.0f - timesteps[b], TAU_MIN_F);
        size_t o = 3 * (size_t)warp;
        float kx = keypoints[o + 0];
        float ky = keypoints[o + 1];
        float kz = keypoints[o + 2];
        g_x[0][warp] = make_float4(kx + tau * (acc0 + head_b[0]),
                                   ky + tau * (acc1 + head_b[1]),
                                   kz + tau * (acc2 + head_b[2]), 0.f);
    }
}

// ---------------------------------------------------------------------------
// Kernel 2: x_next = x_cur  (Jacobi double-buffer init)
// ---------------------------------------------------------------------------
__global__ void copy_kernel(int cur, int nxt) {
    int i = blockIdx.x * blockDim.x + threadIdx.x;
    if (i < BB * NN) g_x[nxt][i] = g_x[cur][i];
}

// ---------------------------------------------------------------------------
// Kernel 3: one XPBD Jacobi iteration. Thread per edge, loop over batches.
// Reads x_cur, scatter-adds into x_next via VECTOR red.global.add.v4.f32
// (2 REDs per edge-batch instead of 6 scalar ones).
// ---------------------------------------------------------------------------
__device__ __forceinline__ void red_add_v4(float4* ptr, float x, float y,
                                           float z) {
    asm volatile(
        "red.global.add.v4.f32 [%0], {%1, %2, %3, %4};"
        :: "l"(ptr), "f"(x), "f"(y), "f"(z), "f"(0.0f)
        : "memory");
}

__global__ void __launch_bounds__(256) edge_kernel(
    const int* __restrict__ edge_index, const float* __restrict__ rest,
    int cur, int nxt) {
    int e = blockIdx.x * blockDim.x + threadIdx.x;
    if (e >= EE) return;
    int s = edge_index[e];
    int d = edge_index[EE + e];
    float L0 = rest[e];

#pragma unroll
    for (int b = 0; b < BB; b++) {
        float4 xs = g_x[cur][b * NN + s];
        float4 xd = g_x[cur][b * NN + d];
        float dx = xs.x - xd.x;
        float dy = xs.y - xd.y;
        float dz = xs.z - xd.z;
        float d2 = fmaf(dx, dx, fmaf(dy, dy, dz * dz)) + 1e-24f;
        float rinv = rsqrtf(d2);         // 1/dist (eps 1e-9 in ref: <=1e-7 rel)
        float dist = d2 * rinv;
        // f = -(dist - L0)/2 * (1/dist)
        float f = (L0 - dist) * 0.5f * rinv;
        float cx = fminf(fmaxf(f * dx, -MAX_CORR_F), MAX_CORR_F);
        float cy = fminf(fmaxf(f * dy, -MAX_CORR_F), MAX_CORR_F);
        float cz = fminf(fmaxf(f * dz, -MAX_CORR_F), MAX_CORR_F);
        red_add_v4(&g_x[nxt][b * NN + s], cx, cy, cz);
        red_add_v4(&g_x[nxt][b * NN + d], -cx, -cy, -cz);
    }
}

// ---------------------------------------------------------------------------
// Kernel 4: v_eff = (x_corrected - keypoints) / tau
// ---------------------------------------------------------------------------
__global__ void final_kernel(const float* __restrict__ keypoints,
                             const float* __restrict__ timesteps,
                             float* __restrict__ out, int cur) {
    int i = blockIdx.x * blockDim.x + threadIdx.x;
    if (i >= BB * NN) return;
    int b = i / NN;
    float tau = fmaxf(1.0f - timesteps[b], TAU_MIN_F);
    float4 x = g_x[cur][i];
    size_t o = 3 * (size_t)i;
    out[o + 0] = (x.x - keypoints[o + 0]) / tau;
    out[o + 1] = (x.y - keypoints[o + 1]) / tau;
    out[o + 2] = (x.z - keypoints[o + 2]) / tau;
}

extern "C" void kernel_launch(void* const* d_in, const int* in_sizes, int n_in,
                              void* d_out, int out_size) {
    const float* keypoints = (const float*)d_in[0];
    const float* timesteps = (const float*)d_in[1];
    const float* hand_tokens = (const float*)d_in[2];
    const float* head_w = (const float*)d_in[3];
    const float* head_b = (const float*)d_in[4];
    const int* edge_index = (const int*)d_in[5];
    const float* rest = (const float*)d_in[6];
    float* out = (float*)d_out;

    const int rows = BB * NN;  // 200000

    // Phase 1: prediction head (warp per row)
    {
        long long threads = (long long)rows * 32;
        int blk = 256;
        int grid = (int)((threads + blk - 1) / blk);
        pred_kernel<<<grid, blk>>>(keypoints, timesteps, hand_tokens, head_w,
                                   head_b);
    }

    // Phase 2: XPBD Jacobi iterations
    int cur = 0;
    for (int it = 0; it < XPBD_ITERS_I; it++) {
        int nxt = cur ^ 1;
        copy_kernel<<<(rows + 255) / 256, 256>>>(cur, nxt);
        edge_kernel<<<(EE + 255) / 256, 256>>>(edge_index, rest, cur, nxt);
        cur = nxt;
    }

    // Phase 3: effective velocity
    final_kernel<<<(rows + 255) / 256, 256>>>(keypoints, timesteps, out, cur);
}